// round 2
// baseline (speedup 1.0000x reference)
#include <cuda_runtime.h>

// Problem constants (fixed shapes per reference)
#define MAXN 100000
#define MAXE 1600000

// Scratch (device globals — no allocation allowed)
__device__ int   g_is64;            // 1 if edge_index buffer is int64, 0 if int32
__device__ int   g_deg[MAXN];
__device__ float g_dinv[MAXN];
__device__ int   g_src[MAXE];
__device__ int   g_dst[MAXE];
__device__ float g_norm[MAXE];
__device__ float g_xw[MAXN * 64];   // x @ W1 (pre-bias)
__device__ float g_h [MAXN * 64];   // agg1 accumulator, then relu'd hidden
__device__ float g_hw[MAXN * 16];   // h @ W2 (pre-bias)

// ---------------------------------------------------------------------------
// 0) detect edge_index dtype: int64 little-endian => odd 32-bit words all zero
__global__ void k_detect(const unsigned* __restrict__ w) {
    __shared__ int any;
    if (threadIdx.x == 0) any = 0;
    __syncthreads();
    for (int i = threadIdx.x; i < 2048; i += blockDim.x)
        if (w[2 * i + 1] != 0u) any = 1;   // benign race: only writes 1
    __syncthreads();
    if (threadIdx.x == 0) g_is64 = (any == 0) ? 1 : 0;
}

// 1) zero accumulators (graph replays re-run this, so results are deterministic)
__global__ void k_zero(float* __restrict__ out, int n) {
    int i = blockIdx.x * blockDim.x + threadIdx.x;
    if (i < n * 64) g_h[i] = 0.0f;
    if (i < n * 16) out[i] = 0.0f;
    if (i < n)      g_deg[i] = 0;
}

// 2) decode edges (either dtype), bounds-guard, degree count
__global__ void k_deg(const void* __restrict__ eiv, int e, int n) {
    int i = blockIdx.x * blockDim.x + threadIdx.x;
    if (i >= e) return;
    int s, d;
    if (g_is64) {
        const long long* ei = (const long long*)eiv;
        s = (int)ei[i];
        d = (int)ei[(long long)e + i];
    } else {
        const int* ei = (const int*)eiv;
        s = ei[i];
        d = ei[e + i];
    }
    if ((unsigned)s < (unsigned)n && (unsigned)d < (unsigned)n) {
        g_src[i] = s;
        g_dst[i] = d;
        atomicAdd(&g_deg[d], 1);
    } else {                    // never expected; keeps us crash-proof
        g_src[i] = 0;
        g_dst[i] = 0;
        g_norm[i] = 0.0f;       // k_norm will overwrite only valid edges? no:
        // mark via dst sentinel instead: use norm=0 path below
    }
}

// 3) dinv = rsqrt(deg + 1)   (+1 = self loop)
__global__ void k_dinv(int n) {
    int i = blockIdx.x * blockDim.x + threadIdx.x;
    if (i < n) g_dinv[i] = rsqrtf((float)g_deg[i] + 1.0f);
}

// 4) per-edge normalization (recomputed for all edges; invalid edges have
//    src=dst=0 and contribute 0 only if flagged — instead we re-guard here)
__global__ void k_norm(const void* __restrict__ eiv, int e, int n) {
    int i = blockIdx.x * blockDim.x + threadIdx.x;
    if (i >= e) return;
    // validity re-check straight from source buffer (cheap, cached)
    int s, d;
    if (g_is64) {
        const long long* ei = (const long long*)eiv;
        s = (int)ei[i];
        d = (int)ei[(long long)e + i];
    } else {
        const int* ei = (const int*)eiv;
        s = ei[i];
        d = ei[e + i];
    }
    bool ok = (unsigned)s < (unsigned)n && (unsigned)d < (unsigned)n;
    g_norm[i] = ok ? g_dinv[g_src[i]] * g_dinv[g_dst[i]] : 0.0f;
}

// 5) GEMM1: g_xw = x @ W1   (x: [n,64], W1: [64,64])
__global__ void k_gemm1(const float* __restrict__ x, const float* __restrict__ W, int n) {
    __shared__ float Wsh[64 * 64];
    __shared__ float Xsh[4][64];
    int tj = threadIdx.x;   // 0..63 -> output feature
    int tr = threadIdx.y;   // 0..3  -> row in tile
    int tid = tr * 64 + tj;
    for (int i = tid; i < 64 * 64; i += 256) Wsh[i] = W[i];
    int row = blockIdx.x * 4 + tr;
    if (row < n) Xsh[tr][tj] = x[row * 64 + tj];
    __syncthreads();
    if (row >= n) return;
    float acc = 0.0f;
    #pragma unroll
    for (int k = 0; k < 64; k++)
        acc += Xsh[tr][k] * Wsh[k * 64 + tj];
    g_xw[row * 64 + tj] = acc;
}

// 6) layer-1 scatter: h[dst] += xw[src] * norm   (1 thread per edge-feature)
__global__ void k_scatter64(int e) {
    int i = blockIdx.x * blockDim.x + threadIdx.x;   // e*64 = 102.4M fits in int
    if (i >= e * 64) return;
    int ed = i >> 6;
    int f  = i & 63;
    float nv = g_norm[ed];
    float v = g_xw[g_src[ed] * 64 + f] * nv;
    atomicAdd(&g_h[g_dst[ed] * 64 + f], v);
}

// 7) self-loop + bias + ReLU:  h = relu(agg1 + xw*dinv^2 + b1)
__global__ void k_relubias(const float* __restrict__ b1, int n) {
    int i = blockIdx.x * blockDim.x + threadIdx.x;
    if (i >= n * 64) return;
    int r = i >> 6;
    int f = i & 63;
    float di = g_dinv[r];
    float v = g_h[i] + g_xw[i] * di * di + b1[f];
    g_h[i] = v > 0.0f ? v : 0.0f;
}

// 8) GEMM2: g_hw = h @ W2   (h: [n,64], W2: [64,16])
__global__ void k_gemm2(const float* __restrict__ W, int n) {
    __shared__ float Wsh[64 * 16];
    __shared__ float Xsh[16][65];    // pad to kill bank conflicts
    int tx = threadIdx.x;   // 0..15 -> output feature
    int ty = threadIdx.y;   // 0..15 -> row in tile
    int tid = ty * 16 + tx;
    for (int i = tid; i < 64 * 16; i += 256) Wsh[i] = W[i];
    int row = blockIdx.x * 16 + ty;
    if (row < n)
        for (int k = tx; k < 64; k += 16) Xsh[ty][k] = g_h[row * 64 + k];
    __syncthreads();
    if (row >= n) return;
    float acc = 0.0f;
    #pragma unroll
    for (int k = 0; k < 64; k++)
        acc += Xsh[ty][k] * Wsh[k * 16 + tx];
    g_hw[row * 16 + tx] = acc;
}

// 9) layer-2 scatter into d_out
__global__ void k_scatter16(float* __restrict__ out, int e) {
    int i = blockIdx.x * blockDim.x + threadIdx.x;   // e*16 = 25.6M
    if (i >= e * 16) return;
    int ed = i >> 4;
    int f  = i & 15;
    float v = g_hw[g_src[ed] * 16 + f] * g_norm[ed];
    atomicAdd(&out[g_dst[ed] * 16 + f], v);
}

// 10) self-loop + bias epilogue
__global__ void k_final(float* __restrict__ out, const float* __restrict__ b2, int n) {
    int i = blockIdx.x * blockDim.x + threadIdx.x;
    if (i >= n * 16) return;
    int r = i >> 4;
    int f = i & 15;
    float di = g_dinv[r];
    out[i] += g_hw[i] * di * di + b2[f];
}

extern "C" void kernel_launch(void* const* d_in, const int* in_sizes, int n_in,
                              void* d_out, int out_size) {
    const float* x  = (const float*)d_in[0];
    const void*  ei = (const void*)d_in[1];
    const float* W1 = (const float*)d_in[2];
    const float* b1 = (const float*)d_in[3];
    const float* W2 = (const float*)d_in[4];
    const float* b2 = (const float*)d_in[5];
    float* out = (float*)d_out;

    int n = in_sizes[0] / 64;   // 100000
    int e = in_sizes[1] / 2;    // 1600000
    if (n > MAXN) n = MAXN;
    if (e > MAXE) e = MAXE;

    const int T = 256;
    k_detect   <<<1, 256>>>((const unsigned*)ei);
    k_zero     <<<(n * 64 + T - 1) / T, T>>>(out, n);
    k_deg      <<<(e + T - 1) / T, T>>>(ei, e, n);
    k_dinv     <<<(n + T - 1) / T, T>>>(n);
    k_norm     <<<(e + T - 1) / T, T>>>(ei, e, n);
    k_gemm1    <<<(n + 3) / 4, dim3(64, 4)>>>(x, W1, n);
    k_scatter64<<<(e * 64 + T - 1) / T, T>>>(e);
    k_relubias <<<(n * 64 + T - 1) / T, T>>>(b1, n);
    k_gemm2    <<<(n + 15) / 16, dim3(16, 16)>>>(W2, n);
    k_scatter16<<<(e * 16 + T - 1) / T, T>>>(out, e);
    k_final    <<<(n * 16 + T - 1) / T, T>>>(out, b2, n);
}

// round 3
// speedup vs baseline: 2.3199x; 2.3199x over previous
#include <cuda_runtime.h>

#define MAXN 100000
#define MAXE 1600000
#define SCAN_B 512
#define NB1 ((MAXN + SCAN_B - 1) / SCAN_B)   // 196

// Scratch (device globals — no allocation allowed)
__device__ int   g_is64;
__device__ int   g_ninvalid;
__device__ int   g_deg[MAXN];
__device__ float g_dinv[MAXN];
__device__ int   g_src[MAXE];
__device__ int   g_dst[MAXE];
__device__ int   g_csr[MAXE];          // src indices grouped by dst
__device__ int   g_rowstart[MAXN + 1];
__device__ int   g_cursor[MAXN];
__device__ int   g_bsum[256];          // block sums for scan (NB1 <= 256)
__device__ float g_xw[MAXN * 64];      // (x @ W1) * dinv[row]
__device__ float g_h [MAXN * 64];      // hidden after relu
__device__ float g_hw[MAXN * 16];      // (h @ W2) * dinv[row]

// ---------------------------------------------------------------------------
// 0) detect edge_index dtype: int64 little-endian => odd 32-bit words all zero
__global__ void k_detect(const unsigned* __restrict__ w) {
    __shared__ int any;
    if (threadIdx.x == 0) any = 0;
    __syncthreads();
    for (int i = threadIdx.x; i < 2048; i += blockDim.x)
        if (w[2 * i + 1] != 0u) any = 1;
    __syncthreads();
    if (threadIdx.x == 0) g_is64 = (any == 0) ? 1 : 0;
}

// 1) zero histogram state (re-run on every graph replay => deterministic)
__global__ void k_zero(int n) {
    int i = blockIdx.x * blockDim.x + threadIdx.x;
    if (i < n) g_deg[i] = 0;
    if (i == 0) g_ninvalid = 0;
}

// 2) decode edges (either dtype), bounds-guard, degree histogram
__global__ void k_deg(const void* __restrict__ eiv, int e, int n) {
    int i = blockIdx.x * blockDim.x + threadIdx.x;
    if (i >= e) return;
    int s, d;
    if (g_is64) {
        const long long* ei = (const long long*)eiv;
        s = (int)ei[i];
        d = (int)ei[(long long)e + i];
    } else {
        const int* ei = (const int*)eiv;
        s = ei[i];
        d = ei[e + i];
    }
    if ((unsigned)s < (unsigned)n && (unsigned)d < (unsigned)n) {
        g_src[i] = s;
        g_dst[i] = d;
        atomicAdd(&g_deg[d], 1);
    } else {                    // never expected; crash-proofing
        g_src[i] = -1;
        g_dst[i] = -1;
        atomicAdd(&g_ninvalid, 1);
    }
}

// 3) dinv = rsqrt(deg + 1)   (+1 = self loop)
__global__ void k_dinv(int n) {
    int i = blockIdx.x * blockDim.x + threadIdx.x;
    if (i < n) g_dinv[i] = rsqrtf((float)g_deg[i] + 1.0f);
}

// 4a) block-local exclusive scan of deg -> rowstart (partial) + block sums
__global__ void k_scan1(int n) {
    __shared__ int sh[SCAN_B];
    int t = threadIdx.x;
    int g = blockIdx.x * SCAN_B + t;
    int v = (g < n) ? g_deg[g] : 0;
    sh[t] = v;
    __syncthreads();
    for (int off = 1; off < SCAN_B; off <<= 1) {
        int tmp = (t >= off) ? sh[t - off] : 0;
        __syncthreads();
        if (t >= off) sh[t] += tmp;
        __syncthreads();
    }
    if (g < n) g_rowstart[g] = sh[t] - v;                 // exclusive, block-local
    if (t == SCAN_B - 1) g_bsum[blockIdx.x] = sh[t];      // block total
}

// 4b) exclusive scan of block sums (single block; NB1 <= 256)
__global__ void k_scan2(int nb) {
    __shared__ int sh[256];
    int t = threadIdx.x;
    int v = (t < nb) ? g_bsum[t] : 0;
    sh[t] = v;
    __syncthreads();
    for (int off = 1; off < 256; off <<= 1) {
        int tmp = (t >= off) ? sh[t - off] : 0;
        __syncthreads();
        if (t >= off) sh[t] += tmp;
        __syncthreads();
    }
    if (t < nb) g_bsum[t] = sh[t] - v;                    // exclusive
}

// 4c) add block offsets; init cursors; set rowstart[n]
__global__ void k_scan3(int n, int e) {
    int g = blockIdx.x * blockDim.x + threadIdx.x;
    if (g < n) {
        int r = g_rowstart[g] + g_bsum[g / SCAN_B];
        g_rowstart[g] = r;
        g_cursor[g] = r;
    }
    if (g == 0) g_rowstart[n] = e - g_ninvalid;
}

// 5) fill CSR: slot per edge via cursor atomics (int, spread -> cheap)
__global__ void k_fill(int e) {
    int i = blockIdx.x * blockDim.x + threadIdx.x;
    if (i >= e) return;
    int s = g_src[i];
    if (s < 0) return;
    int pos = atomicAdd(&g_cursor[g_dst[i]], 1);
    g_csr[pos] = s;
}

// 6) GEMM1: g_xw = (x @ W1) * dinv[row]
__global__ void k_gemm1(const float* __restrict__ x, const float* __restrict__ W, int n) {
    __shared__ float Wsh[64 * 64];
    __shared__ float Xsh[4][64];
    int tj = threadIdx.x;
    int tr = threadIdx.y;
    int tid = tr * 64 + tj;
    for (int i = tid; i < 64 * 64; i += 256) Wsh[i] = W[i];
    int row = blockIdx.x * 4 + tr;
    if (row < n) Xsh[tr][tj] = x[row * 64 + tj];
    __syncthreads();
    if (row >= n) return;
    float acc = 0.0f;
    #pragma unroll
    for (int k = 0; k < 64; k++)
        acc += Xsh[tr][k] * Wsh[k * 64 + tj];
    g_xw[row * 64 + tj] = acc * g_dinv[row];
}

// 7) layer-1 aggregation: one warp per node, lane owns a float2 of 64 feats.
//    h[d] = relu(dinv[d] * (sum_{src in CSR[d]} xws[src] + xws[d]) + b1)
__global__ void k_agg1(const float* __restrict__ b1, int n) {
    int warp = (blockIdx.x * blockDim.x + threadIdx.x) >> 5;
    int lane = threadIdx.x & 31;
    if (warp >= n) return;
    int beg = g_rowstart[warp];
    int end = g_rowstart[warp + 1];
    const float2* xws = (const float2*)g_xw;
    float ax0 = 0.f, ay0 = 0.f, ax1 = 0.f, ay1 = 0.f;
    float ax2 = 0.f, ay2 = 0.f, ax3 = 0.f, ay3 = 0.f;
    int j = beg;
    for (; j + 4 <= end; j += 4) {
        int s0 = g_csr[j], s1 = g_csr[j + 1], s2 = g_csr[j + 2], s3 = g_csr[j + 3];
        float2 a0 = xws[s0 * 32 + lane];
        float2 a1 = xws[s1 * 32 + lane];
        float2 a2 = xws[s2 * 32 + lane];
        float2 a3 = xws[s3 * 32 + lane];
        ax0 += a0.x; ay0 += a0.y;
        ax1 += a1.x; ay1 += a1.y;
        ax2 += a2.x; ay2 += a2.y;
        ax3 += a3.x; ay3 += a3.y;
    }
    for (; j < end; j++) {
        float2 a = xws[g_csr[j] * 32 + lane];
        ax0 += a.x; ay0 += a.y;
    }
    float2 self = xws[warp * 32 + lane];
    float di = g_dinv[warp];
    float vx = di * (ax0 + ax1 + ax2 + ax3 + self.x) + b1[2 * lane];
    float vy = di * (ay0 + ay1 + ay2 + ay3 + self.y) + b1[2 * lane + 1];
    g_h[warp * 64 + 2 * lane]     = vx > 0.f ? vx : 0.f;
    g_h[warp * 64 + 2 * lane + 1] = vy > 0.f ? vy : 0.f;
}

// 8) GEMM2: g_hw = (h @ W2) * dinv[row]
__global__ void k_gemm2(const float* __restrict__ W, int n) {
    __shared__ float Wsh[64 * 16];
    __shared__ float Xsh[16][65];
    int tx = threadIdx.x;
    int ty = threadIdx.y;
    int tid = ty * 16 + tx;
    for (int i = tid; i < 64 * 16; i += 256) Wsh[i] = W[i];
    int row = blockIdx.x * 16 + ty;
    if (row < n)
        for (int k = tx; k < 64; k += 16) Xsh[ty][k] = g_h[row * 64 + k];
    __syncthreads();
    if (row >= n) return;
    float acc = 0.0f;
    #pragma unroll
    for (int k = 0; k < 64; k++)
        acc += Xsh[ty][k] * Wsh[k * 16 + tx];
    g_hw[row * 16 + tx] = acc * g_dinv[row];
}

// 9) layer-2 aggregation: one thread per (node, feature); half-warp coalesced.
__global__ void k_agg2(float* __restrict__ out, const float* __restrict__ b2, int n) {
    int i = blockIdx.x * blockDim.x + threadIdx.x;
    if (i >= n * 16) return;
    int node = i >> 4;
    int f    = i & 15;
    int beg = g_rowstart[node];
    int end = g_rowstart[node + 1];
    float a0 = 0.f, a1 = 0.f, a2 = 0.f, a3 = 0.f;
    int j = beg;
    for (; j + 4 <= end; j += 4) {
        a0 += g_hw[g_csr[j]     * 16 + f];
        a1 += g_hw[g_csr[j + 1] * 16 + f];
        a2 += g_hw[g_csr[j + 2] * 16 + f];
        a3 += g_hw[g_csr[j + 3] * 16 + f];
    }
    for (; j < end; j++)
        a0 += g_hw[g_csr[j] * 16 + f];
    float di = g_dinv[node];
    out[i] = di * (a0 + a1 + a2 + a3 + g_hw[node * 16 + f]) + b2[f];
}

extern "C" void kernel_launch(void* const* d_in, const int* in_sizes, int n_in,
                              void* d_out, int out_size) {
    const float* x  = (const float*)d_in[0];
    const void*  ei = (const void*)d_in[1];
    const float* W1 = (const float*)d_in[2];
    const float* b1 = (const float*)d_in[3];
    const float* W2 = (const float*)d_in[4];
    const float* b2 = (const float*)d_in[5];
    float* out = (float*)d_out;

    int n = in_sizes[0] / 64;   // 100000
    int e = in_sizes[1] / 2;    // 1600000
    if (n > MAXN) n = MAXN;
    if (e > MAXE) e = MAXE;
    int nb = (n + SCAN_B - 1) / SCAN_B;   // <= 196

    const int T = 256;
    k_detect<<<1, 256>>>((const unsigned*)ei);
    k_zero  <<<(n + T - 1) / T, T>>>(n);
    k_deg   <<<(e + T - 1) / T, T>>>(ei, e, n);
    k_dinv  <<<(n + T - 1) / T, T>>>(n);
    k_scan1 <<<nb, SCAN_B>>>(n);
    k_scan2 <<<1, 256>>>(nb);
    k_scan3 <<<(n + T - 1) / T, T>>>(n, e);
    k_fill  <<<(e + T - 1) / T, T>>>(e);
    k_gemm1 <<<(n + 3) / 4, dim3(64, 4)>>>(x, W1, n);
    k_agg1  <<<(n * 32 + T - 1) / T, T>>>(b1, n);
    k_gemm2 <<<(n + 15) / 16, dim3(16, 16)>>>(W2, n);
    k_agg2  <<<(n * 16 + T - 1) / T, T>>>(out, b2, n);
}

// round 4
// speedup vs baseline: 3.7549x; 1.6185x over previous
#include <cuda_runtime.h>

#define MAXN 100000
#define MAXE 1600000
#define SB 512                         // scan block size
#define MAXNB ((MAXN + SB - 1) / SB)   // 196

// Scratch (device globals — no allocation allowed)
__device__ int       g_any = 0;        // sticky: 1 => edge buffer is int32
__device__ int       g_deg[MAXN];
__device__ float     g_dinv[MAXN];
__device__ int       g_src[MAXE];
__device__ int       g_dst[MAXE];
__device__ int       g_csr[MAXE];      // src indices grouped by dst
__device__ int       g_rowstart[MAXN + 1];
__device__ int       g_cursor[MAXN];
__device__ long long g_bpack[256];     // (blockSum<<1)|1 publications
__device__ float     g_xw[MAXN * 64];  // (x @ W1) * dinv[row]
__device__ float     g_h [MAXN * 64];  // hidden after relu
__device__ float     g_hw[MAXN * 16];  // (h @ W2) * dinv[row]

// ---------------------------------------------------------------------------
// 1) init: zero deg + scan flags; sticky dtype detect (input constant across
//    replays, so g_any only ever transitions 0->1 consistently)
__global__ void k_init(const unsigned* __restrict__ w, int n) {
    int i = blockIdx.x * blockDim.x + threadIdx.x;
    if (i < n) g_deg[i] = 0;
    if (i < 256) g_bpack[i] = 0;
    if (i < 2048 && w[2 * i + 1] != 0u) atomicOr(&g_any, 1);
}

// 2) decode edges (either dtype), bounds-guard, degree histogram
__global__ void k_deg(const void* __restrict__ eiv, int e, int n) {
    int i = blockIdx.x * blockDim.x + threadIdx.x;
    if (i >= e) return;
    int s, d;
    if (g_any == 0) {   // int64 little-endian
        const long long* ei = (const long long*)eiv;
        s = (int)ei[i];
        d = (int)ei[(long long)e + i];
    } else {
        const int* ei = (const int*)eiv;
        s = ei[i];
        d = ei[e + i];
    }
    if ((unsigned)s < (unsigned)n && (unsigned)d < (unsigned)n) {
        g_src[i] = s;
        g_dst[i] = d;
        atomicAdd(&g_deg[d], 1);
    } else {
        g_src[i] = -1;
        g_dst[i] = -1;
    }
}

// 3) single-kernel exclusive scan (chained, warp-parallel lookback) + dinv +
//    cursor init + rowstart[n]
__global__ void k_scan(int n, int nb) {
    __shared__ int sh[SB];
    __shared__ int s_pref;
    int t = threadIdx.x, b = blockIdx.x;
    int g = b * SB + t;
    int deg = (g < n) ? g_deg[g] : 0;
    sh[t] = deg;
    __syncthreads();
    for (int off = 1; off < SB; off <<= 1) {
        int tmp = (t >= off) ? sh[t - off] : 0;
        __syncthreads();
        if (t >= off) sh[t] += tmp;
        __syncthreads();
    }
    int incl = sh[t];
    if (t == SB - 1)
        *((volatile long long*)&g_bpack[b]) = (((long long)incl) << 1) | 1;
    if (t < 32) {          // warp 0: sum predecessor block totals
        int acc = 0;
        for (int base = 0; base < b; base += 32) {
            int p = base + t;
            long long pk = 0;
            if (p < b) {
                do { pk = *((volatile long long*)&g_bpack[p]); } while (!(pk & 1));
            }
            acc += (int)(pk >> 1);
        }
        #pragma unroll
        for (int o = 16; o; o >>= 1) acc += __shfl_xor_sync(0xffffffffu, acc, o);
        if (t == 0) s_pref = acc;
    }
    __syncthreads();
    int excl = s_pref + incl - deg;
    if (g < n) {
        g_rowstart[g] = excl;
        g_cursor[g]   = excl;
        g_dinv[g]     = rsqrtf((float)deg + 1.0f);
    }
    if (b == nb - 1 && t == SB - 1) g_rowstart[n] = s_pref + incl;
}

// 4) GEMM1: g_xw = (x @ W1) * dinv[row].  4x4 register tile per thread.
//    block (16,16): 64 rows x 64 cols per block.
__global__ void k_gemm1(const float* __restrict__ x, const float* __restrict__ W, int n) {
    __shared__ float4 Wsh4[64 * 16];     // [k][j4]
    __shared__ float  Xsh[64][68];       // stride 68: 16B-aligned rows, no conflicts
    int tx = threadIdx.x;                // 0..15 -> col group (4 cols)
    int ty = threadIdx.y;                // 0..15 -> row group (4 rows)
    int tid = ty * 16 + tx;
    int row0 = blockIdx.x * 64;
    const float4* W4 = (const float4*)W;
    const float4* x4 = (const float4*)x;
    for (int i = tid; i < 1024; i += 256) Wsh4[i] = W4[i];
    for (int i = tid; i < 1024; i += 256) {
        int r = i >> 4, c4 = i & 15;
        float4 v = (row0 + r < n) ? x4[(row0 + r) * 16 + c4]
                                  : make_float4(0.f, 0.f, 0.f, 0.f);
        *((float4*)&Xsh[r][c4 * 4]) = v;
    }
    __syncthreads();
    int r0 = ty * 4;
    float4 a0 = {0,0,0,0}, a1 = {0,0,0,0}, a2 = {0,0,0,0}, a3 = {0,0,0,0};
    #pragma unroll
    for (int k = 0; k < 64; k++) {
        float4 w = Wsh4[k * 16 + tx];
        float x0 = Xsh[r0 + 0][k], x1 = Xsh[r0 + 1][k];
        float x2 = Xsh[r0 + 2][k], x3 = Xsh[r0 + 3][k];
        a0.x += x0 * w.x; a0.y += x0 * w.y; a0.z += x0 * w.z; a0.w += x0 * w.w;
        a1.x += x1 * w.x; a1.y += x1 * w.y; a1.z += x1 * w.z; a1.w += x1 * w.w;
        a2.x += x2 * w.x; a2.y += x2 * w.y; a2.z += x2 * w.z; a2.w += x2 * w.w;
        a3.x += x3 * w.x; a3.y += x3 * w.y; a3.z += x3 * w.z; a3.w += x3 * w.w;
    }
    float4* xw4 = (float4*)g_xw;
    #pragma unroll
    for (int i = 0; i < 4; i++) {
        int row = row0 + r0 + i;
        if (row < n) {
            float di = g_dinv[row];
            float4 a = (i == 0) ? a0 : (i == 1) ? a1 : (i == 2) ? a2 : a3;
            a.x *= di; a.y *= di; a.z *= di; a.w *= di;
            xw4[row * 16 + tx] = a;
        }
    }
}

// 5) fill CSR via cursor atomics
__global__ void k_fill(int e) {
    int i = blockIdx.x * blockDim.x + threadIdx.x;
    if (i >= e) return;
    int s = g_src[i];
    if (s < 0) return;
    int pos = atomicAdd(&g_cursor[g_dst[i]], 1);
    g_csr[pos] = s;
}

// 6) layer-1 aggregation: one warp per node, lane owns a float2 of 64 feats.
__global__ void k_agg1(const float* __restrict__ b1, int n) {
    int warp = (blockIdx.x * blockDim.x + threadIdx.x) >> 5;
    int lane = threadIdx.x & 31;
    if (warp >= n) return;
    int beg = g_rowstart[warp];
    int end = g_rowstart[warp + 1];
    const float2* xws = (const float2*)g_xw;
    float ax0 = 0.f, ay0 = 0.f, ax1 = 0.f, ay1 = 0.f;
    float ax2 = 0.f, ay2 = 0.f, ax3 = 0.f, ay3 = 0.f;
    int j = beg;
    for (; j + 4 <= end; j += 4) {
        int s0 = g_csr[j], s1 = g_csr[j + 1], s2 = g_csr[j + 2], s3 = g_csr[j + 3];
        float2 a0 = xws[s0 * 32 + lane];
        float2 a1 = xws[s1 * 32 + lane];
        float2 a2 = xws[s2 * 32 + lane];
        float2 a3 = xws[s3 * 32 + lane];
        ax0 += a0.x; ay0 += a0.y;
        ax1 += a1.x; ay1 += a1.y;
        ax2 += a2.x; ay2 += a2.y;
        ax3 += a3.x; ay3 += a3.y;
    }
    for (; j < end; j++) {
        float2 a = xws[g_csr[j] * 32 + lane];
        ax0 += a.x; ay0 += a.y;
    }
    float2 self = xws[warp * 32 + lane];
    float di = g_dinv[warp];
    float vx = di * (ax0 + ax1 + ax2 + ax3 + self.x) + b1[2 * lane];
    float vy = di * (ay0 + ay1 + ay2 + ay3 + self.y) + b1[2 * lane + 1];
    g_h[warp * 64 + 2 * lane]     = vx > 0.f ? vx : 0.f;
    g_h[warp * 64 + 2 * lane + 1] = vy > 0.f ? vy : 0.f;
}

// 7) GEMM2: g_hw = (h @ W2) * dinv[row].  1 row x 4 cols per thread.
//    block (4,64): 64 rows per block.
__global__ void k_gemm2(const float* __restrict__ W, int n) {
    __shared__ float4 Wsh4[64 * 4];      // [k][j4]
    __shared__ float  Xsh[64][65];
    int tx = threadIdx.x;                // 0..3 -> col group
    int ty = threadIdx.y;                // 0..63 -> row
    int tid = ty * 4 + tx;
    int row0 = blockIdx.x * 64;
    const float4* W4 = (const float4*)W;
    for (int i = tid; i < 256; i += 256) Wsh4[i] = W4[i];
    for (int i = tid; i < 4096; i += 256) {
        int r = i >> 6, c = i & 63;
        Xsh[r][c] = (row0 + r < n) ? g_h[(row0 + r) * 64 + c] : 0.f;
    }
    __syncthreads();
    float4 acc = {0, 0, 0, 0};
    #pragma unroll
    for (int k = 0; k < 64; k++) {
        float xv = Xsh[ty][k];
        float4 w = Wsh4[k * 4 + tx];
        acc.x += xv * w.x; acc.y += xv * w.y; acc.z += xv * w.z; acc.w += xv * w.w;
    }
    int row = row0 + ty;
    if (row < n) {
        float di = g_dinv[row];
        acc.x *= di; acc.y *= di; acc.z *= di; acc.w *= di;
        ((float4*)g_hw)[row * 4 + tx] = acc;
    }
}

// 8) layer-2 aggregation: one thread per (node, feature)
__global__ void k_agg2(float* __restrict__ out, const float* __restrict__ b2, int n) {
    int i = blockIdx.x * blockDim.x + threadIdx.x;
    if (i >= n * 16) return;
    int node = i >> 4;
    int f    = i & 15;
    int beg = g_rowstart[node];
    int end = g_rowstart[node + 1];
    float a0 = 0.f, a1 = 0.f, a2 = 0.f, a3 = 0.f;
    int j = beg;
    for (; j + 4 <= end; j += 4) {
        a0 += g_hw[g_csr[j]     * 16 + f];
        a1 += g_hw[g_csr[j + 1] * 16 + f];
        a2 += g_hw[g_csr[j + 2] * 16 + f];
        a3 += g_hw[g_csr[j + 3] * 16 + f];
    }
    for (; j < end; j++)
        a0 += g_hw[g_csr[j] * 16 + f];
    float di = g_dinv[node];
    out[i] = di * (a0 + a1 + a2 + a3 + g_hw[node * 16 + f]) + b2[f];
}

extern "C" void kernel_launch(void* const* d_in, const int* in_sizes, int n_in,
                              void* d_out, int out_size) {
    const float* x  = (const float*)d_in[0];
    const void*  ei = (const void*)d_in[1];
    const float* W1 = (const float*)d_in[2];
    const float* b1 = (const float*)d_in[3];
    const float* W2 = (const float*)d_in[4];
    const float* b2 = (const float*)d_in[5];
    float* out = (float*)d_out;

    int n = in_sizes[0] / 64;   // 100000
    int e = in_sizes[1] / 2;    // 1600000
    if (n > MAXN) n = MAXN;
    if (e > MAXE) e = MAXE;
    int nb = (n + SB - 1) / SB;

    const int T = 256;
    k_init <<<(n + T - 1) / T, T>>>((const unsigned*)ei, n);
    k_deg  <<<(e + T - 1) / T, T>>>(ei, e, n);
    k_scan <<<nb, SB>>>(n, nb);
    k_gemm1<<<(n + 63) / 64, dim3(16, 16)>>>(x, W1, n);   // profiled slot (#4)
    k_fill <<<(e + T - 1) / T, T>>>(e);
    k_agg1 <<<(n * 32 + T - 1) / T, T>>>(b1, n);
    k_gemm2<<<(n + 63) / 64, dim3(4, 64)>>>(W2, n);
    k_agg2 <<<(n * 16 + T - 1) / T, T>>>(out, b2, n);
}